// round 8
// baseline (speedup 1.0000x reference)
#include <cuda_runtime.h>
#include <cuda_bf16.h>
#include <math.h>
#include <stdint.h>

// Problem constants
#define NB  8
#define CIN 512
#define KC  512
#define HHW 16384
#define KK  19
#define EPSBN 1e-5f
#define QSCALE 0.044194173824159216f   // 512^-0.5

// GEMM tiling (mma.sync path; compute_103-safe)
#define BM 128
#define BN 128
#define BK 32
#define NKC (CIN / BK)      // 16 k-chunks
#define ROWB 40             // bf16 elems per smem row (80 bytes incl 16B pad)
#define SM_ARR (128 * ROWB) // elems per operand array per stage
#define GSM_TOT (2 * 4 * SM_ARR * 2)   // 81920 bytes

// ---------------------------------------------------------------------------
// Device scratch
// ---------------------------------------------------------------------------
__device__ __nv_bfloat16 g_xt_hi[(size_t)NB * HHW * CIN];   // xt, later ctx
__device__ __nv_bfloat16 g_xt_lo[(size_t)NB * HHW * CIN];
__device__ __nv_bfloat16 g_q1_hi[(size_t)NB * HHW * KC];
__device__ __nv_bfloat16 g_q1_lo[(size_t)NB * HHW * KC];
__device__ float         g_q2   [(size_t)NB * HHW * KC];
__device__ __nv_bfloat16 g_w_hi[3 * 512 * 512];
__device__ __nv_bfloat16 g_w_lo[3 * 512 * 512];
__device__ float g_k1[NB * KC * KK];
__device__ float g_k [NB * KC * KK];
__device__ float g_v [NB * KC * KK];
__device__ float g_scale[6 * 512];   // 0=p1 1=p2 2=o1 3=o2 4=d 5=u
__device__ float g_shift[6 * 512];

// ---------------------------------------------------------------------------
// Helpers (sm_80-level features only)
// ---------------------------------------------------------------------------
__device__ __forceinline__ uint32_t smem_u32(const void* p) {
    uint32_t a;
    asm("{ .reg .u64 t; cvta.to.shared.u64 t, %1; cvt.u32.u64 %0, t; }" : "=r"(a) : "l"(p));
    return a;
}
__device__ __forceinline__ void cp_async16(void* dst, const void* src) {
    uint32_t d = smem_u32(dst);
    asm volatile("cp.async.cg.shared.global [%0], [%1], 16;" :: "r"(d), "l"(src));
}
#define CP_COMMIT() asm volatile("cp.async.commit_group;" ::: "memory")
#define CP_WAIT1()  asm volatile("cp.async.wait_group 1;" ::: "memory")
#define CP_WAIT0()  asm volatile("cp.async.wait_group 0;" ::: "memory")

__device__ __forceinline__ void mma16816(float* d, const uint32_t* a, const uint32_t* b) {
    asm volatile(
        "mma.sync.aligned.m16n8k16.row.col.f32.bf16.bf16.f32 "
        "{%0,%1,%2,%3},{%4,%5,%6,%7},{%8,%9},{%0,%1,%2,%3};"
        : "+f"(d[0]), "+f"(d[1]), "+f"(d[2]), "+f"(d[3])
        : "r"(a[0]), "r"(a[1]), "r"(a[2]), "r"(a[3]), "r"(b[0]), "r"(b[1]));
}
__device__ __forceinline__ void ldm_x4(uint32_t* r, uint32_t addr) {
    asm volatile("ldmatrix.sync.aligned.m8n8.x4.shared.b16 {%0,%1,%2,%3}, [%4];"
        : "=r"(r[0]), "=r"(r[1]), "=r"(r[2]), "=r"(r[3]) : "r"(addr));
}

// ---------------------------------------------------------------------------
// BN folding, all 6 tags in one launch (grid.y = tag)
// ---------------------------------------------------------------------------
__global__ void bn_prep_all(
    const float* g0, const float* b0, const float* m0, const float* v0,
    const float* g1, const float* b1, const float* m1, const float* v1,
    const float* g2, const float* b2, const float* m2, const float* v2,
    const float* g3, const float* b3, const float* m3, const float* v3,
    const float* g4, const float* b4, const float* m4, const float* v4,
    const float* g5, const float* b5, const float* m5, const float* v5)
{
    const float* G[6] = {g0, g1, g2, g3, g4, g5};
    const float* B[6] = {b0, b1, b2, b3, b4, b5};
    const float* M[6] = {m0, m1, m2, m3, m4, m5};
    const float* V[6] = {v0, v1, v2, v3, v4, v5};
    int tag = blockIdx.y;
    int i = blockIdx.x * blockDim.x + threadIdx.x;
    if (i < 512) {
        float s = G[tag][i] * rsqrtf(V[tag][i] + EPSBN);
        g_scale[tag * 512 + i] = s;
        g_shift[tag * 512 + i] = B[tag][i] - M[tag][i] * s;
    }
}

// Weight hi/lo split: all 3 weights, grid.y = widx
__global__ void w_split_all(const float* w0, const float* w1, const float* w2)
{
    const float* W[3] = {w0, w1, w2};
    int widx = blockIdx.y;
    int i = blockIdx.x * blockDim.x + threadIdx.x;
    if (i < 512 * 512) {
        float v = W[widx][i];
        __nv_bfloat16 h = __float2bfloat16_rn(v);
        __nv_bfloat16 l = __float2bfloat16_rn(v - __bfloat162float(h));
        g_w_hi[widx * 262144 + i] = h;
        g_w_lo[widx * 262144 + i] = l;
    }
}

// Input transpose + split: x[n][c][p] -> xt[(n*HHW+p)*512 + c]
__global__ void split_transpose_kernel(const float* __restrict__ x)
{
    __shared__ float t[32][33];
    const int n = blockIdx.z, p0 = blockIdx.x * 32, c0 = blockIdx.y * 32;
    const int tx = threadIdx.x, ty = threadIdx.y;     // 32 x 8
    const float* X = x + (size_t)n * CIN * HHW;
#pragma unroll
    for (int r = ty; r < 32; r += 8)
        t[r][tx] = X[(size_t)(c0 + r) * HHW + p0 + tx];
    __syncthreads();
#pragma unroll
    for (int r = ty; r < 32; r += 8) {
        float v = t[tx][r];                           // c = c0+tx, p = p0+r
        __nv_bfloat16 h = __float2bfloat16_rn(v);
        __nv_bfloat16 l = __float2bfloat16_rn(v - __bfloat162float(h));
        size_t o = ((size_t)n * HHW + p0 + r) * 512 + c0 + tx;
        g_xt_hi[o] = h;
        g_xt_lo[o] = l;
    }
}

// ---------------------------------------------------------------------------
// GEMM via mma.sync bf16 hi/lo 3-pass, ldmatrix loads, staged epilogue.
//   D[px 128][out 128] = A[px][ch] * W[out][ch]^T, K=512
// ---------------------------------------------------------------------------
#define STG_STRIDE_BF 136    // bf16 elems/row (272B): store banks (4g+q) distinct
#define STG_STRIDE_F  132    // fp32 elems/row (528B)

template<int MODE>
__global__ void __launch_bounds__(256, 2) gemm_mma(
    const __nv_bfloat16* __restrict__ Ah, const __nv_bfloat16* __restrict__ Al,
    const __nv_bfloat16* __restrict__ Bh, const __nv_bfloat16* __restrict__ Bl,
    float* __restrict__ out_f,
    __nv_bfloat16* __restrict__ out_h, __nv_bfloat16* __restrict__ out_l,
    int tag)
{
    extern __shared__ __nv_bfloat16 smem[];   // mainloop: [2 stages][4 arrays][SM_ARR]
    const int tid = threadIdx.x;
    const int nB  = blockIdx.z;
    const int m0  = blockIdx.x * BM;
    const int n0  = blockIdx.y * BN;

    const __nv_bfloat16* gA[2] = { Ah + ((size_t)nB * HHW + m0) * 512,
                                   Al + ((size_t)nB * HHW + m0) * 512 };
    const __nv_bfloat16* gB[2] = { Bh + (size_t)n0 * 512,
                                   Bl + (size_t)n0 * 512 };

    auto load_stage = [&](int stage, int kc) {
        __nv_bfloat16* st = smem + stage * 4 * SM_ARR;
#pragma unroll
        for (int it = 0; it < 8; it++) {
            int i   = tid + it * 256;
            int arr = i >> 9;          // 0,1: A hi/lo  2,3: B hi/lo
            int idx = i & 511;
            int r   = idx >> 2;
            int c   = idx & 3;
            const __nv_bfloat16* src = (arr < 2 ? gA[arr] : gB[arr - 2])
                                       + (size_t)r * 512 + kc * BK + c * 8;
            cp_async16(st + arr * SM_ARR + r * ROWB + c * 8, src);
        }
        CP_COMMIT();
    };

    const int lane = tid & 31;
    const int q = lane & 3, g = lane >> 2;
    const int wid = tid >> 5;
    const int wm = wid & 1;        // m half (64 rows)
    const int wn = wid >> 1;       // n quarter (32 cols)

    const uint32_t sbase = smem_u32(smem);
    const uint32_t aOff = ((uint32_t)(wm * 64 + (lane & 15)) * ROWB
                           + (uint32_t)((lane >> 4) & 1) * 8) * 2;
    const uint32_t bOff = ((uint32_t)(wn * 32 + (lane & 7) + ((lane >> 4) & 1) * 8) * ROWB
                           + (uint32_t)((lane >> 3) & 1) * 8) * 2;

    float acc[4][4][4];
#pragma unroll
    for (int i = 0; i < 4; i++)
#pragma unroll
        for (int j = 0; j < 4; j++)
#pragma unroll
            for (int k = 0; k < 4; k++) acc[i][j][k] = 0.0f;

    load_stage(0, 0);

    for (int kc = 0; kc < NKC; kc++) {
        if (kc + 1 < NKC) { load_stage((kc + 1) & 1, kc + 1); CP_WAIT1(); }
        else              { CP_WAIT0(); }
        __syncthreads();

        const uint32_t stb = sbase + (uint32_t)(kc & 1) * (4 * SM_ARR * 2);
        const uint32_t ahB = stb + aOff;
        const uint32_t alB = stb + 1 * (SM_ARR * 2) + aOff;
        const uint32_t bhB = stb + 2 * (SM_ARR * 2) + bOff;
        const uint32_t blB = stb + 3 * (SM_ARR * 2) + bOff;

#pragma unroll
        for (int ks = 0; ks < 2; ks++) {
            const uint32_t kb = (uint32_t)ks * 32;
            uint32_t aF[4][4], bF[4][2];

#pragma unroll
            for (int mf = 0; mf < 4; mf++)
                ldm_x4(aF[mf], ahB + (uint32_t)mf * (16 * ROWB * 2) + kb);
            ldm_x4(&bF[0][0], bhB + kb);
            ldm_x4(&bF[2][0], bhB + 16 * ROWB * 2 + kb);
#pragma unroll
            for (int mf = 0; mf < 4; mf++)
#pragma unroll
                for (int nf = 0; nf < 4; nf++)
                    mma16816(acc[mf][nf], aF[mf], bF[nf]);

            ldm_x4(&bF[0][0], blB + kb);
            ldm_x4(&bF[2][0], blB + 16 * ROWB * 2 + kb);
#pragma unroll
            for (int mf = 0; mf < 4; mf++)
#pragma unroll
                for (int nf = 0; nf < 4; nf++)
                    mma16816(acc[mf][nf], aF[mf], bF[nf]);

#pragma unroll
            for (int mf = 0; mf < 4; mf++)
                ldm_x4(aF[mf], alB + (uint32_t)mf * (16 * ROWB * 2) + kb);
            ldm_x4(&bF[0][0], bhB + kb);
            ldm_x4(&bF[2][0], bhB + 16 * ROWB * 2 + kb);
#pragma unroll
            for (int mf = 0; mf < 4; mf++)
#pragma unroll
                for (int nf = 0; nf < 4; nf++)
                    mma16816(acc[mf][nf], aF[mf], bF[nf]);
        }
        __syncthreads();
    }
    // mainloop done; smem free for staging (post final __syncthreads)

    // ---- epilogue: BN + ReLU ----
    if (MODE == 0) {
        // stage hi/lo bf16 tiles [128][STG_STRIDE_BF], then coalesced copy
        __nv_bfloat16* Th = smem;
        __nv_bfloat16* Tl = smem + 128 * STG_STRIDE_BF;
#pragma unroll
        for (int nf = 0; nf < 4; nf++) {
            const int chl = wn * 32 + nf * 8 + q * 2;
            const int ch0 = n0 + chl;
            const float sc0 = g_scale[tag * 512 + ch0],     sh0 = g_shift[tag * 512 + ch0];
            const float sc1 = g_scale[tag * 512 + ch0 + 1], sh1 = g_shift[tag * 512 + ch0 + 1];
#pragma unroll
            for (int mf = 0; mf < 4; mf++) {
#pragma unroll
                for (int half = 0; half < 2; half++) {
                    const int pxl = wm * 64 + mf * 16 + g + half * 8;
                    float v0 = acc[mf][nf][half * 2 + 0] * sc0 + sh0;
                    float v1 = acc[mf][nf][half * 2 + 1] * sc1 + sh1;
                    v0 = v0 > 0.0f ? v0 : 0.0f;
                    v1 = v1 > 0.0f ? v1 : 0.0f;
                    __nv_bfloat16 h0 = __float2bfloat16_rn(v0);
                    __nv_bfloat16 h1 = __float2bfloat16_rn(v1);
                    __nv_bfloat16 l0 = __float2bfloat16_rn(v0 - __bfloat162float(h0));
                    __nv_bfloat16 l1 = __float2bfloat16_rn(v1 - __bfloat162float(h1));
                    uint32_t ph = (uint32_t)*(uint16_t*)&h0 | ((uint32_t)*(uint16_t*)&h1 << 16);
                    uint32_t pl = (uint32_t)*(uint16_t*)&l0 | ((uint32_t)*(uint16_t*)&l1 << 16);
                    *(uint32_t*)(Th + pxl * STG_STRIDE_BF + chl) = ph;
                    *(uint32_t*)(Tl + pxl * STG_STRIDE_BF + chl) = pl;
                }
            }
        }
        __syncthreads();
        {
            const int row = tid >> 1, hf = tid & 1;     // 128 rows x 2 halves
            size_t go = ((size_t)nB * HHW + m0 + row) * 512 + n0 + hf * 64;
            const uint4* sh = (const uint4*)(Th + row * STG_STRIDE_BF + hf * 64);
            const uint4* sl = (const uint4*)(Tl + row * STG_STRIDE_BF + hf * 64);
            uint4* dh = (uint4*)(out_h + go);
            uint4* dl = (uint4*)(out_l + go);
#pragma unroll
            for (int i = 0; i < 8; i++) dh[i] = sh[i];
#pragma unroll
            for (int i = 0; i < 8; i++) dl[i] = sl[i];
        }
    } else if (MODE == 1) {
        // stage fp32 tile [128][STG_STRIDE_F], then coalesced copy
        float* Tf = (float*)smem;
#pragma unroll
        for (int nf = 0; nf < 4; nf++) {
            const int chl = wn * 32 + nf * 8 + q * 2;
            const int ch0 = n0 + chl;
            const float sc0 = g_scale[tag * 512 + ch0],     sh0 = g_shift[tag * 512 + ch0];
            const float sc1 = g_scale[tag * 512 + ch0 + 1], sh1 = g_shift[tag * 512 + ch0 + 1];
#pragma unroll
            for (int mf = 0; mf < 4; mf++) {
#pragma unroll
                for (int half = 0; half < 2; half++) {
                    const int pxl = wm * 64 + mf * 16 + g + half * 8;
                    float v0 = acc[mf][nf][half * 2 + 0] * sc0 + sh0;
                    float v1 = acc[mf][nf][half * 2 + 1] * sc1 + sh1;
                    v0 = v0 > 0.0f ? v0 : 0.0f;
                    v1 = v1 > 0.0f ? v1 : 0.0f;
                    *(float2*)(Tf + pxl * STG_STRIDE_F + chl) = make_float2(v0, v1);
                }
            }
        }
        __syncthreads();
        {
            const int row = tid >> 1, hf = tid & 1;
            size_t go = ((size_t)nB * HHW + m0 + row) * 512 + n0 + hf * 64;
            const uint4* sf = (const uint4*)(Tf + row * STG_STRIDE_F + hf * 64);
            uint4* df = (uint4*)(out_f + go);
#pragma unroll
            for (int i = 0; i < 16; i++) df[i] = sf[i];
        }
    } else {
        // MODE 2: scatter [ch][px] (32B-contiguous per quarter-warp)
#pragma unroll
        for (int nf = 0; nf < 4; nf++) {
            const int ch0 = n0 + wn * 32 + nf * 8 + q * 2;
            const float sc0 = g_scale[tag * 512 + ch0],     sh0 = g_shift[tag * 512 + ch0];
            const float sc1 = g_scale[tag * 512 + ch0 + 1], sh1 = g_shift[tag * 512 + ch0 + 1];
#pragma unroll
            for (int mf = 0; mf < 4; mf++) {
#pragma unroll
                for (int half = 0; half < 2; half++) {
                    const int px = m0 + wm * 64 + mf * 16 + g + half * 8;
                    float v0 = acc[mf][nf][half * 2 + 0] * sc0 + sh0;
                    float v1 = acc[mf][nf][half * 2 + 1] * sc1 + sh1;
                    v0 = v0 > 0.0f ? v0 : 0.0f;
                    v1 = v1 > 0.0f ? v1 : 0.0f;
                    out_f[((size_t)nB * 512 + ch0)     * HHW + px] = v0;
                    out_f[((size_t)nB * 512 + ch0 + 1) * HHW + px] = v1;
                }
            }
        }
    }
}

// ---------------------------------------------------------------------------
// Proxy path (tiny)
// ---------------------------------------------------------------------------
__global__ void __launch_bounds__(128) kv1_kernel(
    const float* __restrict__ proxy, const float* __restrict__ wo1, const float* __restrict__ wd)
{
    const int n = blockIdx.y;
    const int m = blockIdx.x * 128 + threadIdx.x;
    __shared__ float ps[CIN * KK];
    const float* P = proxy + (size_t)n * CIN * KK;
    for (int i = threadIdx.x; i < CIN * KK; i += 128) ps[i] = P[i];
    __syncthreads();

    float aK[KK], aV[KK];
#pragma unroll
    for (int j = 0; j < KK; j++) { aK[j] = 0.0f; aV[j] = 0.0f; }
    for (int c = 0; c < CIN; c++) {
        float w1 = wo1[(size_t)m * CIN + c];
        float w2 = wd [(size_t)m * CIN + c];
#pragma unroll
        for (int j = 0; j < KK; j++) {
            float p = ps[c * KK + j];
            aK[j] += w1 * p; aV[j] += w2 * p;
        }
    }
    float s1 = g_scale[2 * 512 + m], h1 = g_shift[2 * 512 + m];
    float s2 = g_scale[4 * 512 + m], h2 = g_shift[4 * 512 + m];
    float* K1 = g_k1 + ((size_t)n * KC + m) * KK;
    float* Vv = g_v  + ((size_t)n * KC + m) * KK;
#pragma unroll
    for (int j = 0; j < KK; j++) {
        float vk = aK[j] * s1 + h1; K1[j] = vk > 0.0f ? vk : 0.0f;
        float vv = aV[j] * s2 + h2; Vv[j] = vv > 0.0f ? vv : 0.0f;
    }
}

__global__ void __launch_bounds__(128) kv2_kernel(const float* __restrict__ wo2)
{
    const int n = blockIdx.y;
    const int m = blockIdx.x * 128 + threadIdx.x;
    __shared__ float ps[KC * KK];
    const float* K1 = g_k1 + (size_t)n * KC * KK;
    for (int i = threadIdx.x; i < KC * KK; i += 128) ps[i] = K1[i];
    __syncthreads();
    float aK[KK];
#pragma unroll
    for (int j = 0; j < KK; j++) aK[j] = 0.0f;
    for (int c = 0; c < KC; c++) {
        float w = wo2[(size_t)m * KC + c];
#pragma unroll
        for (int j = 0; j < KK; j++) aK[j] += w * ps[c * KK + j];
    }
    float s = g_scale[3 * 512 + m], h = g_shift[3 * 512 + m];
    float* Ko = g_k + ((size_t)n * KC + m) * KK;
#pragma unroll
    for (int j = 0; j < KK; j++) {
        float vk = aK[j] * s + h; Ko[j] = vk > 0.0f ? vk : 0.0f;
    }
}

// ---------------------------------------------------------------------------
// Fused attention: sim = q.k * scale -> softmax(19) -> ctx = attn.v
// ---------------------------------------------------------------------------
#define ATT_SMEM ((512 * KK + 512 * 33) * 4)
__device__ __forceinline__ void softmax19(float* a) {
    float mx = -1e30f;
#pragma unroll
    for (int j = 0; j < KK; j++) { a[j] *= QSCALE; mx = fmaxf(mx, a[j]); }
    float s = 0.0f;
#pragma unroll
    for (int j = 0; j < KK; j++) { a[j] = __expf(a[j] - mx); s += a[j]; }
    float inv = 1.0f / s;
#pragma unroll
    for (int j = 0; j < KK; j++) a[j] *= inv;
}

__global__ void __launch_bounds__(256) attn_fused_kernel(
    const float* __restrict__ q2,
    __nv_bfloat16* __restrict__ ctx_h, __nv_bfloat16* __restrict__ ctx_l)
{
    extern __shared__ float sm[];
    float* ks = sm;                 // [512*19]
    float* qt = sm + 512 * KK;      // [512][33]
    const int n = blockIdx.y;
    const int p0 = blockIdx.x * 512;
    const int t = threadIdx.x;

    const float* Kn = g_k + (size_t)n * KC * KK;
    for (int i = t; i < KC * KK; i += 256) ks[i] = Kn[i];
    __syncthreads();

    float a0[KK], a1[KK];
#pragma unroll
    for (int j = 0; j < KK; j++) { a0[j] = 0.0f; a1[j] = 0.0f; }

    const float* Q = q2 + ((size_t)n * HHW + p0) * 512;
    for (int cc = 0; cc < 16; cc++) {
#pragma unroll
        for (int qq = 0; qq < 64; qq++) {
            int idx = t + qq * 256;
            int r = idx >> 5, c = idx & 31;
            qt[r * 33 + c] = Q[(size_t)r * 512 + cc * 32 + c];
        }
        __syncthreads();
        for (int c = 0; c < 32; c++) {
            float q0 = qt[t * 33 + c];
            float q1 = qt[(t + 256) * 33 + c];
            const float* kr = ks + (cc * 32 + c) * KK;
#pragma unroll
            for (int j = 0; j < KK; j++) {
                float kv = kr[j];
                a0[j] += q0 * kv; a1[j] += q1 * kv;
            }
        }
        __syncthreads();
    }
    softmax19(a0);
    softmax19(a1);

    __syncthreads();
    const float* Vn = g_v + (size_t)n * KC * KK;
    for (int i = t; i < KC * KK; i += 256) ks[i] = Vn[i];
    __syncthreads();

    size_t o0 = ((size_t)n * HHW + p0 + t) * 512;
    size_t o1 = ((size_t)n * HHW + p0 + t + 256) * 512;
    for (int c0 = 0; c0 < 512; c0 += 8) {
        uint32_t h0[4], l0[4], h1[4], l1[4];
#pragma unroll
        for (int pr = 0; pr < 4; pr++) {
            float s0a = 0, s0b = 0, s1a = 0, s1b = 0;
            const float* vra = ks + (c0 + 2 * pr) * KK;
            const float* vrb = ks + (c0 + 2 * pr + 1) * KK;
#pragma unroll
            for (int j = 0; j < KK; j++) {
                float va = vra[j], vb = vrb[j];
                s0a += a0[j] * va; s0b += a0[j] * vb;
                s1a += a1[j] * va; s1b += a1[j] * vb;
            }
            __nv_bfloat16 ha = __float2bfloat16_rn(s0a), hb = __float2bfloat16_rn(s0b);
            __nv_bfloat16 la = __float2bfloat16_rn(s0a - __bfloat162float(ha));
            __nv_bfloat16 lb = __float2bfloat16_rn(s0b - __bfloat162float(hb));
            h0[pr] = (uint32_t)*(uint16_t*)&ha | ((uint32_t)*(uint16_t*)&hb << 16);
            l0[pr] = (uint32_t)*(uint16_t*)&la | ((uint32_t)*(uint16_t*)&lb << 16);
            __nv_bfloat16 hc = __float2bfloat16_rn(s1a), hd = __float2bfloat16_rn(s1b);
            __nv_bfloat16 lc = __float2bfloat16_rn(s1a - __bfloat162float(hc));
            __nv_bfloat16 ld = __float2bfloat16_rn(s1b - __bfloat162float(hd));
            h1[pr] = (uint32_t)*(uint16_t*)&hc | ((uint32_t)*(uint16_t*)&hd << 16);
            l1[pr] = (uint32_t)*(uint16_t*)&lc | ((uint32_t)*(uint16_t*)&ld << 16);
        }
        *(uint4*)(ctx_h + o0 + c0) = *(uint4*)h0;
        *(uint4*)(ctx_l + o0 + c0) = *(uint4*)l0;
        *(uint4*)(ctx_h + o1 + c0) = *(uint4*)h1;
        *(uint4*)(ctx_l + o1 + c0) = *(uint4*)l1;
    }
}

// ---------------------------------------------------------------------------
// Launch. Harness issues ~2 launches before ours; ncu (-s 5 -c 1) profiles
// global idx 5 = our local idx 3 = gemm0.
// Order: [0] bn_all [1] w_split_all [2] transpose [3] gemm0 [4] gemm1
//        [5] kv1 [6] kv2 [7] attn [8] gemm2
// ---------------------------------------------------------------------------
extern "C" void kernel_launch(void* const* d_in, const int* in_sizes, int n_in,
                              void* d_out, int out_size)
{
    const float* in[32];
    for (int i = 0; i < 32; i++) in[i] = (const float*)d_in[i];

    const float *x, *proxy, *wp1, *wp2, *wo1, *wo2, *wd, *wu;
    const float *bn[6][4];
    if (in_sizes[3] == 262144) {       // dict order
        x = in[0]; proxy = in[1];
        wp1 = in[2]; wp2 = in[3]; wo1 = in[4]; wo2 = in[5]; wd = in[6]; wu = in[7];
        for (int t = 0; t < 6; t++)
            for (int q = 0; q < 4; q++) bn[t][q] = in[8 + t * 4 + q];
    } else {                           // signature order
        x = in[0]; proxy = in[1];
        wp1 = in[2]; wp2 = in[7]; wo1 = in[12]; wo2 = in[17]; wd = in[22]; wu = in[27];
        const int base[6] = {3, 8, 13, 18, 23, 28};
        for (int t = 0; t < 6; t++)
            for (int q = 0; q < 4; q++) bn[t][q] = in[base[t] + q];
    }
    float* out = (float*)d_out;

    void *p_xth, *p_xtl, *p_q1h, *p_q1l, *p_q2, *p_wh, *p_wl;
    cudaGetSymbolAddress(&p_xth, g_xt_hi);
    cudaGetSymbolAddress(&p_xtl, g_xt_lo);
    cudaGetSymbolAddress(&p_q1h, g_q1_hi);
    cudaGetSymbolAddress(&p_q1l, g_q1_lo);
    cudaGetSymbolAddress(&p_q2, g_q2);
    cudaGetSymbolAddress(&p_wh, g_w_hi);
    cudaGetSymbolAddress(&p_wl, g_w_lo);
    __nv_bfloat16* xth = (__nv_bfloat16*)p_xth;
    __nv_bfloat16* xtl = (__nv_bfloat16*)p_xtl;
    __nv_bfloat16* q1h = (__nv_bfloat16*)p_q1h;
    __nv_bfloat16* q1l = (__nv_bfloat16*)p_q1l;
    float* q2 = (float*)p_q2;
    __nv_bfloat16* wh = (__nv_bfloat16*)p_wh;
    __nv_bfloat16* wl = (__nv_bfloat16*)p_wl;

    cudaFuncSetAttribute(gemm_mma<0>, cudaFuncAttributeMaxDynamicSharedMemorySize, GSM_TOT);
    cudaFuncSetAttribute(gemm_mma<1>, cudaFuncAttributeMaxDynamicSharedMemorySize, GSM_TOT);
    cudaFuncSetAttribute(gemm_mma<2>, cudaFuncAttributeMaxDynamicSharedMemorySize, GSM_TOT);
    cudaFuncSetAttribute(attn_fused_kernel, cudaFuncAttributeMaxDynamicSharedMemorySize, ATT_SMEM);

    // [0] BN folding (all tags)
    bn_prep_all<<<dim3(2, 6), 256>>>(
        bn[0][0], bn[0][1], bn[0][2], bn[0][3],
        bn[1][0], bn[1][1], bn[1][2], bn[1][3],
        bn[2][0], bn[2][1], bn[2][2], bn[2][3],
        bn[3][0], bn[3][1], bn[3][2], bn[3][3],
        bn[4][0], bn[4][1], bn[4][2], bn[4][3],
        bn[5][0], bn[5][1], bn[5][2], bn[5][3]);

    // [1] all weight splits, [2] input transpose
    w_split_all<<<dim3(1024, 3), 256>>>(wp1, wp2, wu);
    split_transpose_kernel<<<dim3(HHW / 32, 512 / 32, NB), dim3(32, 8)>>>(x);

    dim3 ggrid(HHW / BM, KC / BN, NB);   // (128, 4, 8)
    // [3] gemm0  <-- ncu capture target
    gemm_mma<0><<<ggrid, 256, GSM_TOT>>>(xth, xtl, wh + 0 * 262144, wl + 0 * 262144,
                                         nullptr, q1h, q1l, 0);
    // [4] gemm1
    gemm_mma<1><<<ggrid, 256, GSM_TOT>>>(q1h, q1l, wh + 1 * 262144, wl + 1 * 262144,
                                         q2, nullptr, nullptr, 1);
    // [5][6] proxy path, [7] attention, [8] gemm2
    kv1_kernel<<<dim3(4, NB), 128>>>(proxy, wo1, wd);
    kv2_kernel<<<dim3(4, NB), 128>>>(wo2);
    attn_fused_kernel<<<dim3(HHW / 512, NB), 256, ATT_SMEM>>>(q2, xth, xtl);
    gemm_mma<2><<<ggrid, 256, GSM_TOT>>>(xth, xtl, wh + 2 * 262144, wl + 2 * 262144,
                                         out, nullptr, nullptr, 5);
}

// round 12
// speedup vs baseline: 1.4458x; 1.4458x over previous
#include <cuda_runtime.h>
#include <cuda_fp16.h>
#include <math.h>
#include <stdint.h>

// Problem constants
#define NB  8
#define CIN 512
#define KC  512
#define HHW 16384
#define KK  19
#define EPSBN 1e-5f
#define QSCALE 0.044194173824159216f   // 512^-0.5

// GEMM tiling (mma.sync path; compute_103-safe)
#define BM 128
#define BN 128
#define BK 32
#define NKC (CIN / BK)      // 16 k-chunks
#define ROWB 40             // fp16 elems per smem row (80 bytes incl 16B pad)
#define SM_ARR (128 * ROWB) // elems per operand array per stage
#define GSM_TOT (2 * 3 * SM_ARR * 2)   // 2 stages x 3 arrays (A,Bh,Bl) = 61440 B

// ---------------------------------------------------------------------------
// Device scratch
// ---------------------------------------------------------------------------
__device__ __half g_xt[(size_t)NB * HHW * CIN];   // x transposed fp16; later ctx
__device__ __half g_q1[(size_t)NB * HHW * KC];
__device__ float  g_q2[(size_t)NB * HHW * KC];
__device__ __half g_w_hi[3 * 512 * 512];
__device__ __half g_w_lo[3 * 512 * 512];
__device__ float g_k1[NB * KC * KK];
__device__ float g_k [NB * KC * KK];
__device__ float g_v [NB * KC * KK];
__device__ float g_scale[6 * 512];   // 0=p1 1=p2 2=o1 3=o2 4=d 5=u
__device__ float g_shift[6 * 512];

// ---------------------------------------------------------------------------
// Helpers (sm_80-level features only)
// ---------------------------------------------------------------------------
__device__ __forceinline__ uint32_t smem_u32(const void* p) {
    uint32_t a;
    asm("{ .reg .u64 t; cvta.to.shared.u64 t, %1; cvt.u32.u64 %0, t; }" : "=r"(a) : "l"(p));
    return a;
}
__device__ __forceinline__ void cp_async16(void* dst, const void* src) {
    uint32_t d = smem_u32(dst);
    asm volatile("cp.async.cg.shared.global [%0], [%1], 16;" :: "r"(d), "l"(src));
}
#define CP_COMMIT() asm volatile("cp.async.commit_group;" ::: "memory")
#define CP_WAIT1()  asm volatile("cp.async.wait_group 1;" ::: "memory")
#define CP_WAIT0()  asm volatile("cp.async.wait_group 0;" ::: "memory")

__device__ __forceinline__ void mma16816(float* d, const uint32_t* a, const uint32_t* b) {
    asm volatile(
        "mma.sync.aligned.m16n8k16.row.col.f32.f16.f16.f32 "
        "{%0,%1,%2,%3},{%4,%5,%6,%7},{%8,%9},{%0,%1,%2,%3};"
        : "+f"(d[0]), "+f"(d[1]), "+f"(d[2]), "+f"(d[3])
        : "r"(a[0]), "r"(a[1]), "r"(a[2]), "r"(a[3]), "r"(b[0]), "r"(b[1]));
}
__device__ __forceinline__ void ldm_x4(uint32_t* r, uint32_t addr) {
    asm volatile("ldmatrix.sync.aligned.m8n8.x4.shared.b16 {%0,%1,%2,%3}, [%4];"
        : "=r"(r[0]), "=r"(r[1]), "=r"(r[2]), "=r"(r[3]) : "r"(addr));
}
__device__ __forceinline__ uint32_t pack_half2(float a, float b) {
    __half ha = __float2half_rn(a), hb = __float2half_rn(b);
    return (uint32_t)*(uint16_t*)&ha | ((uint32_t)*(uint16_t*)&hb << 16);
}

// ---------------------------------------------------------------------------
// BN folding, all 6 tags in one launch (grid.y = tag)
// ---------------------------------------------------------------------------
__global__ void bn_prep_all(
    const float* g0, const float* b0, const float* m0, const float* v0,
    const float* g1, const float* b1, const float* m1, const float* v1,
    const float* g2, const float* b2, const float* m2, const float* v2,
    const float* g3, const float* b3, const float* m3, const float* v3,
    const float* g4, const float* b4, const float* m4, const float* v4,
    const float* g5, const float* b5, const float* m5, const float* v5)
{
    const float* G[6] = {g0, g1, g2, g3, g4, g5};
    const float* B[6] = {b0, b1, b2, b3, b4, b5};
    const float* M[6] = {m0, m1, m2, m3, m4, m5};
    const float* V[6] = {v0, v1, v2, v3, v4, v5};
    int tag = blockIdx.y;
    int i = blockIdx.x * blockDim.x + threadIdx.x;
    if (i < 512) {
        float s = G[tag][i] * rsqrtf(V[tag][i] + EPSBN);
        g_scale[tag * 512 + i] = s;
        g_shift[tag * 512 + i] = B[tag][i] - M[tag][i] * s;
    }
}

// Weight fp16 hi/lo split: all 3 weights, grid.y = widx
__global__ void w_split_all(const float* w0, const float* w1, const float* w2)
{
    const float* W[3] = {w0, w1, w2};
    int widx = blockIdx.y;
    int i = blockIdx.x * blockDim.x + threadIdx.x;
    if (i < 512 * 512) {
        float v = W[widx][i];
        __half h = __float2half_rn(v);
        __half l = __float2half_rn(v - __half2float(h));
        g_w_hi[widx * 262144 + i] = h;
        g_w_lo[widx * 262144 + i] = l;
    }
}

// Input transpose: x[n][c][p] -> xt[(n*HHW+p)*512 + c] (fp16)
__global__ void split_transpose_kernel(const float* __restrict__ x)
{
    __shared__ float t[32][33];
    const int n = blockIdx.z, p0 = blockIdx.x * 32, c0 = blockIdx.y * 32;
    const int tx = threadIdx.x, ty = threadIdx.y;     // 32 x 8
    const float* X = x + (size_t)n * CIN * HHW;
#pragma unroll
    for (int r = ty; r < 32; r += 8)
        t[r][tx] = X[(size_t)(c0 + r) * HHW + p0 + tx];
    __syncthreads();
#pragma unroll
    for (int r = ty; r < 32; r += 8) {
        size_t o = ((size_t)n * HHW + p0 + r) * 512 + c0 + tx;
        g_xt[o] = __float2half_rn(t[tx][r]);
    }
}

// ---------------------------------------------------------------------------
// GEMM via mma.sync fp16, W hi/lo split 2-pass (A*Wh + A*Wl), ldmatrix loads.
//   D[px 128][out 128] = A[px][ch] * W[out][ch]^T, K=512
// 256 threads, warp grid 2(m)x4(n), warp tile 64x32, BK=32, 2-stage cp.async.
// MODE 0: fp16 [px][ch]; MODE 1: fp32 [px][ch]; MODE 2: fp32 [ch][px].
// ---------------------------------------------------------------------------
template<int MODE>
__global__ void __launch_bounds__(256, 2) gemm_mma(
    const __half* __restrict__ A,
    const __half* __restrict__ Bh, const __half* __restrict__ Bl,
    float* __restrict__ out_f, __half* __restrict__ out_h,
    int tag)
{
    extern __shared__ __half smem[];   // [2 stages][3 arrays: A,Bh,Bl][SM_ARR]
    const int tid = threadIdx.x;
    const int nB  = blockIdx.z;
    const int m0  = blockIdx.x * BM;
    const int n0  = blockIdx.y * BN;

    const __half* gA  = A  + ((size_t)nB * HHW + m0) * 512;
    const __half* gBh = Bh + (size_t)n0 * 512;
    const __half* gBl = Bl + (size_t)n0 * 512;

    auto load_stage = [&](int stage, int kc) {
        __half* st = smem + stage * 3 * SM_ARR;
#pragma unroll
        for (int it = 0; it < 6; it++) {
            int i   = tid + it * 256;
            int arr = i >> 9;          // 0: A  1: Bh  2: Bl
            int idx = i & 511;
            int r   = idx >> 2;
            int c   = idx & 3;
            const __half* src = (arr == 0 ? gA : (arr == 1 ? gBh : gBl))
                                + (size_t)r * 512 + kc * BK + c * 8;
            cp_async16(st + arr * SM_ARR + r * ROWB + c * 8, src);
        }
        CP_COMMIT();
    };

    const int lane = tid & 31;
    const int q = lane & 3, g = lane >> 2;
    const int wid = tid >> 5;
    const int wm = wid & 1;        // m half (64 rows)
    const int wn = wid >> 1;       // n quarter (32 cols)

    const uint32_t sbase = smem_u32(smem);
    const uint32_t aOff = ((uint32_t)(wm * 64 + (lane & 15)) * ROWB
                           + (uint32_t)((lane >> 4) & 1) * 8) * 2;
    const uint32_t bOff = ((uint32_t)(wn * 32 + (lane & 7) + ((lane >> 4) & 1) * 8) * ROWB
                           + (uint32_t)((lane >> 3) & 1) * 8) * 2;

    float acc[4][4][4];
#pragma unroll
    for (int i = 0; i < 4; i++)
#pragma unroll
        for (int j = 0; j < 4; j++)
#pragma unroll
            for (int k = 0; k < 4; k++) acc[i][j][k] = 0.0f;

    load_stage(0, 0);

    for (int kc = 0; kc < NKC; kc++) {
        if (kc + 1 < NKC) { load_stage((kc + 1) & 1, kc + 1); CP_WAIT1(); }
        else              { CP_WAIT0(); }
        __syncthreads();

        const uint32_t stb = sbase + (uint32_t)(kc & 1) * (3 * SM_ARR * 2);
        const uint32_t aB  = stb + aOff;
        const uint32_t bhB = stb + 1 * (SM_ARR * 2) + bOff;
        const uint32_t blB = stb + 2 * (SM_ARR * 2) + bOff;

#pragma unroll
        for (int ks = 0; ks < 2; ks++) {
            const uint32_t kb = (uint32_t)ks * 32;
            uint32_t aF[4][4], bF[4][2];

            // A fragments (4 m-frags)
#pragma unroll
            for (int mf = 0; mf < 4; mf++)
                ldm_x4(aF[mf], aB + (uint32_t)mf * (16 * ROWB * 2) + kb);
            // pass 1: A * Wh
            ldm_x4(&bF[0][0], bhB + kb);
            ldm_x4(&bF[2][0], bhB + 16 * ROWB * 2 + kb);
#pragma unroll
            for (int mf = 0; mf < 4; mf++)
#pragma unroll
                for (int nf = 0; nf < 4; nf++)
                    mma16816(acc[mf][nf], aF[mf], bF[nf]);
            // pass 2: A * Wl
            ldm_x4(&bF[0][0], blB + kb);
            ldm_x4(&bF[2][0], blB + 16 * ROWB * 2 + kb);
#pragma unroll
            for (int mf = 0; mf < 4; mf++)
#pragma unroll
                for (int nf = 0; nf < 4; nf++)
                    mma16816(acc[mf][nf], aF[mf], bF[nf]);
        }
        __syncthreads();
    }

    // ---- epilogue: BN + ReLU, direct stores ----
#pragma unroll
    for (int nf = 0; nf < 4; nf++) {
        const int ch0 = n0 + wn * 32 + nf * 8 + q * 2;
        const float sc0 = g_scale[tag * 512 + ch0],     sh0 = g_shift[tag * 512 + ch0];
        const float sc1 = g_scale[tag * 512 + ch0 + 1], sh1 = g_shift[tag * 512 + ch0 + 1];
#pragma unroll
        for (int mf = 0; mf < 4; mf++) {
#pragma unroll
            for (int half = 0; half < 2; half++) {
                const int px = m0 + wm * 64 + mf * 16 + g + half * 8;
                float v0 = acc[mf][nf][half * 2 + 0] * sc0 + sh0;
                float v1 = acc[mf][nf][half * 2 + 1] * sc1 + sh1;
                v0 = v0 > 0.0f ? v0 : 0.0f;
                v1 = v1 > 0.0f ? v1 : 0.0f;
                if (MODE == 0) {
                    size_t o = ((size_t)nB * HHW + px) * 512 + ch0;
                    *(uint32_t*)(out_h + o) = pack_half2(v0, v1);
                } else if (MODE == 1) {
                    size_t o = ((size_t)nB * HHW + px) * 512 + ch0;
                    *(float2*)(out_f + o) = make_float2(v0, v1);
                } else {
                    out_f[((size_t)nB * 512 + ch0)     * HHW + px] = v0;
                    out_f[((size_t)nB * 512 + ch0 + 1) * HHW + px] = v1;
                }
            }
        }
    }
}

// ---------------------------------------------------------------------------
// Proxy path (tiny, fp32)
// ---------------------------------------------------------------------------
__global__ void __launch_bounds__(128) kv1_kernel(
    const float* __restrict__ proxy, const float* __restrict__ wo1, const float* __restrict__ wd)
{
    const int n = blockIdx.y;
    const int m = blockIdx.x * 128 + threadIdx.x;
    __shared__ float ps[CIN * KK];
    const float* P = proxy + (size_t)n * CIN * KK;
    for (int i = threadIdx.x; i < CIN * KK; i += 128) ps[i] = P[i];
    __syncthreads();

    float aK[KK], aV[KK];
#pragma unroll
    for (int j = 0; j < KK; j++) { aK[j] = 0.0f; aV[j] = 0.0f; }
    for (int c = 0; c < CIN; c++) {
        float w1 = wo1[(size_t)m * CIN + c];
        float w2 = wd [(size_t)m * CIN + c];
#pragma unroll
        for (int j = 0; j < KK; j++) {
            float p = ps[c * KK + j];
            aK[j] += w1 * p; aV[j] += w2 * p;
        }
    }
    float s1 = g_scale[2 * 512 + m], h1 = g_shift[2 * 512 + m];
    float s2 = g_scale[4 * 512 + m], h2 = g_shift[4 * 512 + m];
    float* K1 = g_k1 + ((size_t)n * KC + m) * KK;
    float* Vv = g_v  + ((size_t)n * KC + m) * KK;
#pragma unroll
    for (int j = 0; j < KK; j++) {
        float vk = aK[j] * s1 + h1; K1[j] = vk > 0.0f ? vk : 0.0f;
        float vv = aV[j] * s2 + h2; Vv[j] = vv > 0.0f ? vv : 0.0f;
    }
}

__global__ void __launch_bounds__(128) kv2_kernel(const float* __restrict__ wo2)
{
    const int n = blockIdx.y;
    const int m = blockIdx.x * 128 + threadIdx.x;
    __shared__ float ps[KC * KK];
    const float* K1 = g_k1 + (size_t)n * KC * KK;
    for (int i = threadIdx.x; i < KC * KK; i += 128) ps[i] = K1[i];
    __syncthreads();
    float aK[KK];
#pragma unroll
    for (int j = 0; j < KK; j++) aK[j] = 0.0f;
    for (int c = 0; c < KC; c++) {
        float w = wo2[(size_t)m * KC + c];
#pragma unroll
        for (int j = 0; j < KK; j++) aK[j] += w * ps[c * KK + j];
    }
    float s = g_scale[3 * 512 + m], h = g_shift[3 * 512 + m];
    float* Ko = g_k + ((size_t)n * KC + m) * KK;
#pragma unroll
    for (int j = 0; j < KK; j++) {
        float vk = aK[j] * s + h; Ko[j] = vk > 0.0f ? vk : 0.0f;
    }
}

// ---------------------------------------------------------------------------
// Fused attention: sim = q.k * scale -> softmax(19) -> ctx = attn.v (fp16 out)
// ---------------------------------------------------------------------------
#define ATT_SMEM ((512 * KK + 512 * 33) * 4)
__device__ __forceinline__ void softmax19(float* a) {
    float mx = -1e30f;
#pragma unroll
    for (int j = 0; j < KK; j++) { a[j] *= QSCALE; mx = fmaxf(mx, a[j]); }
    float s = 0.0f;
#pragma unroll
    for (int j = 0; j < KK; j++) { a[j] = __expf(a[j] - mx); s += a[j]; }
    float inv = 1.0f / s;
#pragma unroll
    for (int j = 0; j < KK; j++) a[j] *= inv;
}

__global__ void __launch_bounds__(256) attn_fused_kernel(
    const float* __restrict__ q2, __half* __restrict__ ctx)
{
    extern __shared__ float sm[];
    float* ks = sm;                 // [512*19]
    float* qt = sm + 512 * KK;      // [512][33]
    const int n = blockIdx.y;
    const int p0 = blockIdx.x * 512;
    const int t = threadIdx.x;

    const float* Kn = g_k + (size_t)n * KC * KK;
    for (int i = t; i < KC * KK; i += 256) ks[i] = Kn[i];
    __syncthreads();

    float a0[KK], a1[KK];
#pragma unroll
    for (int j = 0; j < KK; j++) { a0[j] = 0.0f; a1[j] = 0.0f; }

    const float* Q = q2 + ((size_t)n * HHW + p0) * 512;
    for (int cc = 0; cc < 16; cc++) {
#pragma unroll
        for (int qq = 0; qq < 64; qq++) {
            int idx = t + qq * 256;
            int r = idx >> 5, c = idx & 31;
            qt[r * 33 + c] = Q[(size_t)r * 512 + cc * 32 + c];
        }
        __syncthreads();
        for (int c = 0; c < 32; c++) {
            float q0 = qt[t * 33 + c];
            float q1 = qt[(t + 256) * 33 + c];
            const float* kr = ks + (cc * 32 + c) * KK;
#pragma unroll
            for (int j = 0; j < KK; j++) {
                float kv = kr[j];
                a0[j] += q0 * kv; a1[j] += q1 * kv;
            }
        }
        __syncthreads();
    }
    softmax19(a0);
    softmax19(a1);

    __syncthreads();
    const float* Vn = g_v + (size_t)n * KC * KK;
    for (int i = t; i < KC * KK; i += 256) ks[i] = Vn[i];
    __syncthreads();

    size_t o0 = ((size_t)n * HHW + p0 + t) * 512;
    size_t o1 = ((size_t)n * HHW + p0 + t + 256) * 512;
    for (int c0 = 0; c0 < 512; c0 += 8) {
        uint32_t h0[4], h1[4];
#pragma unroll
        for (int pr = 0; pr < 4; pr++) {
            float s0a = 0, s0b = 0, s1a = 0, s1b = 0;
            const float* vra = ks + (c0 + 2 * pr) * KK;
            const float* vrb = ks + (c0 + 2 * pr + 1) * KK;
#pragma unroll
            for (int j = 0; j < KK; j++) {
                float va = vra[j], vb = vrb[j];
                s0a += a0[j] * va; s0b += a0[j] * vb;
                s1a += a1[j] * va; s1b += a1[j] * vb;
            }
            h0[pr] = pack_half2(s0a, s0b);
            h1[pr] = pack_half2(s1a, s1b);
        }
        *(uint4*)(ctx + o0 + c0) = *(uint4*)h0;
        *(uint4*)(ctx + o1 + c0) = *(uint4*)h1;
    }
}

// ---------------------------------------------------------------------------
// Launch. Harness issues ~2 launches first; ncu (-s 5 -c 1) = our idx 3 = gemm0.
// Order: [0] bn_all [1] w_split_all [2] transpose [3] gemm0 [4] gemm1
//        [5] kv1 [6] kv2 [7] attn [8] gemm2
// ---------------------------------------------------------------------------
extern "C" void kernel_launch(void* const* d_in, const int* in_sizes, int n_in,
                              void* d_out, int out_size)
{
    const float* in[32];
    for (int i = 0; i < 32; i++) in[i] = (const float*)d_in[i];

    const float *x, *proxy, *wp1, *wp2, *wo1, *wo2, *wd, *wu;
    const float *bn[6][4];
    if (in_sizes[3] == 262144) {       // dict order
        x = in[0]; proxy = in[1];
        wp1 = in[2]; wp2 = in[3]; wo1 = in[4]; wo2 = in[5]; wd = in[6]; wu = in[7];
        for (int t = 0; t < 6; t++)
            for (int q = 0; q < 4; q++) bn[t][q] = in[8 + t * 4 + q];
    } else {                           // signature order
        x = in[0]; proxy = in[1];
        wp1 = in[2]; wp2 = in[7]; wo1 = in[12]; wo2 = in[17]; wd = in[22]; wu = in[27];
        const int base[6] = {3, 8, 13, 18, 23, 28};
        for (int t = 0; t < 6; t++)
            for (int q = 0; q < 4; q++) bn[t][q] = in[base[t] + q];
    }
    float* out = (float*)d_out;

    void *p_xt, *p_q1, *p_q2, *p_wh, *p_wl;
    cudaGetSymbolAddress(&p_xt, g_xt);
    cudaGetSymbolAddress(&p_q1, g_q1);
    cudaGetSymbolAddress(&p_q2, g_q2);
    cudaGetSymbolAddress(&p_wh, g_w_hi);
    cudaGetSymbolAddress(&p_wl, g_w_lo);
    __half* xt = (__half*)p_xt;
    __half* q1 = (__half*)p_q1;
    float* q2 = (float*)p_q2;
    __half* wh = (__half*)p_wh;
    __half* wl = (__half*)p_wl;

    cudaFuncSetAttribute(gemm_mma<0>, cudaFuncAttributeMaxDynamicSharedMemorySize, GSM_TOT);
    cudaFuncSetAttribute(gemm_mma<1>, cudaFuncAttributeMaxDynamicSharedMemorySize, GSM_TOT);
    cudaFuncSetAttribute(gemm_mma<2>, cudaFuncAttributeMaxDynamicSharedMemorySize, GSM_TOT);
    cudaFuncSetAttribute(attn_fused_kernel, cudaFuncAttributeMaxDynamicSharedMemorySize, ATT_SMEM);

    // [0] BN folding (all tags)
    bn_prep_all<<<dim3(2, 6), 256>>>(
        bn[0][0], bn[0][1], bn[0][2], bn[0][3],
        bn[1][0], bn[1][1], bn[1][2], bn[1][3],
        bn[2][0], bn[2][1], bn[2][2], bn[2][3],
        bn[3][0], bn[3][1], bn[3][2], bn[3][3],
        bn[4][0], bn[4][1], bn[4][2], bn[4][3],
        bn[5][0], bn[5][1], bn[5][2], bn[5][3]);

    // [1] weight splits, [2] input transpose
    w_split_all<<<dim3(1024, 3), 256>>>(wp1, wp2, wu);
    split_transpose_kernel<<<dim3(HHW / 32, 512 / 32, NB), dim3(32, 8)>>>(x);

    dim3 ggrid(HHW / BM, KC / BN, NB);   // (128, 4, 8)
    // [3] gemm0  <-- ncu capture target
    gemm_mma<0><<<ggrid, 256, GSM_TOT>>>(xt, wh + 0 * 262144, wl + 0 * 262144,
                                         nullptr, q1, 0);
    // [4] gemm1
    gemm_mma<1><<<ggrid, 256, GSM_TOT>>>(q1, wh + 1 * 262144, wl + 1 * 262144,
                                         q2, nullptr, 1);
    // [5][6] proxy path, [7] attention (ctx -> xt buffer), [8] gemm2
    kv1_kernel<<<dim3(4, NB), 128>>>(proxy, wo1, wd);
    kv2_kernel<<<dim3(4, NB), 128>>>(wo2);
    attn_fused_kernel<<<dim3(HHW / 512, NB), 256, ATT_SMEM>>>(q2, xt);
    gemm_mma<2><<<ggrid, 256, GSM_TOT>>>(xt, wh + 2 * 262144, wl + 2 * 262144,
                                         out, nullptr, 5);
}